// round 2
// baseline (speedup 1.0000x reference)
#include <cuda_runtime.h>
#include <math.h>
#include <stdint.h>

// Problem constants
#define BB 32
#define TT 12
#define NS 325
#define DD 128
#define FF 512
#define MTOK (BB*TT*NS)   // 124800 tokens, divisible by 64

// ---------------- scratch (static device allocations; no runtime alloc) ------
__device__ float g_buf [(size_t)MTOK * 512];   // qkv (stride 384) / ffn hidden (stride 512)
__device__ float g_attn[(size_t)MTOK * 128];   // attention output
__device__ float g_x1  [(size_t)MTOK * 128];   // after temporal block
__device__ float g_x2  [(size_t)MTOK * 128];   // after spatial block
__device__ float g_proj[(size_t)MTOK * 128];   // projection temp

// ---------------- helpers ----------------------------------------------------
__device__ __forceinline__ float gelu_tanh(float x) {
    // jax.nn.gelu default (approximate=True)
    float x3 = x * x * x;
    float t  = tanhf(0.7978845608028654f * (x + 0.044715f * x3));
    return 0.5f * x * (1.0f + t);
}

// ---------------- GEMM: C[M,N] = A[M,K] @ W[N,K]^T + bias (opt. gelu) --------
// 64x64 block tile, 256 threads, 4x4 microtile, K chunked by 32.
// smem stored transposed ([k][row]) so microtile operands are float4 loads.
template<int KDIM, bool DOGELU>
__global__ __launch_bounds__(256, 4) void gemm_tn(
    const float* __restrict__ A, const float* __restrict__ W,
    const float* __restrict__ bias, float* __restrict__ C, int N) {
    __shared__ float As[32][68];
    __shared__ float Ws[32][68];
    const int tx = threadIdx.x & 15;
    const int ty = threadIdx.x >> 4;
    const int m0 = blockIdx.y << 6;
    const int n0 = blockIdx.x << 6;
    const float* Ag = A + (size_t)m0 * KDIM;
    const float* Wg = W + (size_t)n0 * KDIM;

    float acc[4][4] = {};

    for (int k0 = 0; k0 < KDIM; k0 += 32) {
#pragma unroll
        for (int i = 0; i < 8; i++) {
            int idx = threadIdx.x + (i << 8);   // 0..2047
            int r = idx >> 5;
            int k = idx & 31;
            As[k][r] = Ag[(size_t)r * KDIM + k0 + k];
            Ws[k][r] = Wg[(size_t)r * KDIM + k0 + k];
        }
        __syncthreads();
#pragma unroll
        for (int kk = 0; kk < 32; kk++) {
            float4 a4 = *(const float4*)&As[kk][ty << 2];
            float4 b4 = *(const float4*)&Ws[kk][tx << 2];
            float a[4] = {a4.x, a4.y, a4.z, a4.w};
            float b[4] = {b4.x, b4.y, b4.z, b4.w};
#pragma unroll
            for (int i = 0; i < 4; i++)
#pragma unroll
                for (int j = 0; j < 4; j++)
                    acc[i][j] += a[i] * b[j];
        }
        __syncthreads();
    }

    float4 bb = *(const float4*)&bias[n0 + (tx << 2)];
    float bv[4] = {bb.x, bb.y, bb.z, bb.w};
#pragma unroll
    for (int i = 0; i < 4; i++) {
        float4 o;
        float* op = (float*)&o;
#pragma unroll
        for (int j = 0; j < 4; j++) {
            float v = acc[i][j] + bv[j];
            if (DOGELU) v = gelu_tanh(v);
            op[j] = v;
        }
        *(float4*)&C[(size_t)(m0 + (ty << 2) + i) * N + n0 + (tx << 2)] = o;
    }
}

// ---------------- fused residual + LayerNorm (D=128, warp per row) -----------
__global__ __launch_bounds__(256) void res_ln(
    const float* __restrict__ X, const float* __restrict__ P,
    const float* __restrict__ g, const float* __restrict__ b,
    float* __restrict__ O) {
    int row  = blockIdx.x * 8 + (threadIdx.x >> 5);
    int lane = threadIdx.x & 31;
    const float4* x4 = (const float4*)(X + (size_t)row * 128);
    const float4* p4 = (const float4*)(P + (size_t)row * 128);
    float4 xv = x4[lane];
    float4 pv = p4[lane];
    float v[4] = {xv.x + pv.x, xv.y + pv.y, xv.z + pv.z, xv.w + pv.w};
    float s  = v[0] + v[1] + v[2] + v[3];
    float ss = v[0]*v[0] + v[1]*v[1] + v[2]*v[2] + v[3]*v[3];
#pragma unroll
    for (int o = 16; o > 0; o >>= 1) {
        s  += __shfl_xor_sync(0xffffffffu, s,  o);
        ss += __shfl_xor_sync(0xffffffffu, ss, o);
    }
    float mean = s * (1.0f / 128.0f);
    float var  = ss * (1.0f / 128.0f) - mean * mean;
    float rstd = rsqrtf(var + 1e-5f);
    float4 g4 = ((const float4*)g)[lane];
    float4 b4 = ((const float4*)b)[lane];
    float4 o4;
    o4.x = (v[0] - mean) * rstd * g4.x + b4.x;
    o4.y = (v[1] - mean) * rstd * g4.y + b4.y;
    o4.z = (v[2] - mean) * rstd * g4.z + b4.z;
    o4.w = (v[3] - mean) * rstd * g4.w + b4.w;
    ((float4*)(O + (size_t)row * 128))[lane] = o4;
}

// ---------------- temporal attention (seqlen T=12) ---------------------------
// one block per (b, n); smem holds the full 12x384 qkv slab; one thread per
// (head, query) pair => 96 threads.
__global__ __launch_bounds__(96) void temporal_attn(
    const float* __restrict__ QKV, float* __restrict__ Out) {
    __shared__ float s[TT * 384];
    int n = blockIdx.x;
    int b = blockIdx.y;
    for (int idx = threadIdx.x; idx < TT * 384; idx += 96) {
        int t = idx / 384, c = idx % 384;
        s[idx] = QKV[((size_t)(b * TT + t) * NS + n) * 384 + c];
    }
    __syncthreads();

    int h = threadIdx.x / TT;   // 0..7
    int q = threadIdx.x % TT;   // 0..11

    float qr[16];
#pragma unroll
    for (int d = 0; d < 16; d++) qr[d] = s[q * 384 + h * 16 + d];

    float sc[TT];
    float mx = -1e30f;
#pragma unroll
    for (int t2 = 0; t2 < TT; t2++) {
        const float* kr = &s[t2 * 384 + 128 + h * 16];
        float dot = 0.f;
#pragma unroll
        for (int d = 0; d < 16; d++) dot += qr[d] * kr[d];
        sc[t2] = dot * 0.25f;   // 1/sqrt(16)
        mx = fmaxf(mx, sc[t2]);
    }
    float l = 0.f;
#pragma unroll
    for (int t2 = 0; t2 < TT; t2++) {
        sc[t2] = __expf(sc[t2] - mx);
        l += sc[t2];
    }
    float acc[16] = {};
#pragma unroll
    for (int t2 = 0; t2 < TT; t2++) {
        float p = sc[t2];
        const float* vr = &s[t2 * 384 + 256 + h * 16];
#pragma unroll
        for (int d = 0; d < 16; d++) acc[d] += p * vr[d];
    }
    float inv = 1.f / l;
    float* op = &Out[((size_t)(b * TT + q) * NS + n) * 128 + h * 16];
#pragma unroll
    for (int d = 0; d < 16; d++) op[d] = acc[d] * inv;
}

// ---------------- spatial attention (seqlen N=325, +graph bias) --------------
// block = (qtile 0..2, head 0..7, bt 0..383); K/V tiles in smem; one thread
// per query row with online softmax.
__global__ __launch_bounds__(128) void spatial_attn(
    const float* __restrict__ QKV, const float* __restrict__ Bias,
    float* __restrict__ Out) {
    __shared__ float Ks[NS * 16];
    __shared__ float Vs[NS * 16];
    int h  = blockIdx.y;
    int bt = blockIdx.z;
    size_t base = (size_t)bt * NS;
    for (int idx = threadIdx.x; idx < NS * 16; idx += 128) {
        int nn = idx >> 4, d = idx & 15;
        Ks[idx] = QKV[(base + nn) * 384 + 128 + h * 16 + d];
        Vs[idx] = QKV[(base + nn) * 384 + 256 + h * 16 + d];
    }
    __syncthreads();

    int q = blockIdx.x * 128 + threadIdx.x;
    if (q >= NS) return;

    float qr[16];
    const float* qp = &QKV[(base + q) * 384 + h * 16];
#pragma unroll
    for (int d = 0; d < 16; d++) qr[d] = qp[d];

    const float* brow = Bias + (size_t)q * NS;
    float m = -1e30f, l = 0.f;
    float acc[16] = {};
    for (int nn = 0; nn < NS; nn++) {
        const float* kr = &Ks[nn * 16];
        float dot = 0.f;
#pragma unroll
        for (int d = 0; d < 16; d++) dot += qr[d] * kr[d];
        float scv = dot * 0.25f + __ldg(brow + nn);
        if (scv > m) {
            float c = __expf(m - scv);
            l *= c;
#pragma unroll
            for (int d = 0; d < 16; d++) acc[d] *= c;
            m = scv;
        }
        float p = __expf(scv - m);
        l += p;
        const float* vr = &Vs[nn * 16];
#pragma unroll
        for (int d = 0; d < 16; d++) acc[d] += p * vr[d];
    }
    float inv = 1.f / l;
    float* op = &Out[(base + q) * 128 + h * 16];
#pragma unroll
    for (int d = 0; d < 16; d++) op[d] = acc[d] * inv;
}

// ---------------- driver ------------------------------------------------------
extern "C" void kernel_launch(void* const* d_in, const int* in_sizes, int n_in,
                              void* d_out, int out_size) {
    const float* x        = (const float*)d_in[0];
    const float* t_w_in   = (const float*)d_in[1];
    const float* t_b_in   = (const float*)d_in[2];
    const float* t_w_out  = (const float*)d_in[3];
    const float* t_b_out  = (const float*)d_in[4];
    const float* s_w_in   = (const float*)d_in[5];
    const float* s_b_in   = (const float*)d_in[6];
    const float* s_w_out  = (const float*)d_in[7];
    const float* s_b_out  = (const float*)d_in[8];
    const float* g_bias   = (const float*)d_in[9];
    const float* norm_t_g = (const float*)d_in[10];
    const float* norm_t_b = (const float*)d_in[11];
    const float* norm_s_g = (const float*)d_in[12];
    const float* norm_s_b = (const float*)d_in[13];
    const float* ff_w1    = (const float*)d_in[14];
    const float* ff_b1    = (const float*)d_in[15];
    const float* ff_w2    = (const float*)d_in[16];
    const float* ff_b2    = (const float*)d_in[17];
    const float* norm_f_g = (const float*)d_in[18];
    const float* norm_f_b = (const float*)d_in[19];
    float* out = (float*)d_out;

    float *buf, *attn, *x1, *x2, *proj;
    cudaGetSymbolAddress((void**)&buf,  g_buf);
    cudaGetSymbolAddress((void**)&attn, g_attn);
    cudaGetSymbolAddress((void**)&x1,   g_x1);
    cudaGetSymbolAddress((void**)&x2,   g_x2);
    cudaGetSymbolAddress((void**)&proj, g_proj);

    const int MB = MTOK / 64;   // 1950

    // --- temporal block ---
    gemm_tn<128, false><<<dim3(6, MB), 256>>>(x, t_w_in, t_b_in, buf, 384);
    temporal_attn<<<dim3(NS, BB), 96>>>(buf, attn);
    gemm_tn<128, false><<<dim3(2, MB), 256>>>(attn, t_w_out, t_b_out, proj, 128);
    res_ln<<<MTOK / 8, 256>>>(x, proj, norm_t_g, norm_t_b, x1);

    // --- spatial block ---
    gemm_tn<128, false><<<dim3(6, MB), 256>>>(x1, s_w_in, s_b_in, buf, 384);
    spatial_attn<<<dim3(3, 8, BB * TT), 128>>>(buf, g_bias, attn);
    gemm_tn<128, false><<<dim3(2, MB), 256>>>(attn, s_w_out, s_b_out, proj, 128);
    res_ln<<<MTOK / 8, 256>>>(x1, proj, norm_s_g, norm_s_b, x2);

    // --- FFN ---
    gemm_tn<128, true ><<<dim3(8, MB), 256>>>(x2, ff_w1, ff_b1, buf, 512);
    gemm_tn<512, false><<<dim3(2, MB), 256>>>(buf, ff_w2, ff_b2, proj, 128);
    res_ln<<<MTOK / 8, 256>>>(x2, proj, norm_f_g, norm_f_b, out);
}

// round 3
// speedup vs baseline: 2.4944x; 2.4944x over previous
#include <cuda_runtime.h>
#include <math.h>
#include <stdint.h>

// Problem constants
#define BB 32
#define TT 12
#define NS 325
#define DD 128
#define FF 512
#define MTOK (BB*TT*NS)   // 124800 tokens, divisible by 128

// ---------------- scratch (static device allocations; no runtime alloc) ------
__device__ float g_buf  [(size_t)MTOK * 512];
__device__ float g_attn [(size_t)MTOK * 128];
__device__ float g_x1   [(size_t)MTOK * 128];
__device__ float g_x2   [(size_t)MTOK * 128];
__device__ float g_proj [(size_t)MTOK * 128];
__device__ float g_biasT[(size_t)NS * NS];

// ---------------- helpers ----------------------------------------------------
__device__ __forceinline__ float gelu_tanh(float x) {
    float x3 = x * x * x;
    float t  = tanhf(0.7978845608028654f * (x + 0.044715f * x3));
    return 0.5f * x * (1.0f + t);
}

__device__ __forceinline__ uint32_t f2tf32(float x) {
    uint32_t r;
    asm("cvt.rna.tf32.f32 %0, %1;" : "=r"(r) : "f"(x));
    return r;
}

__device__ __forceinline__ void mma_tf32(float c[4], const uint32_t a[4], const uint32_t b[2]) {
    asm volatile(
        "mma.sync.aligned.m16n8k8.row.col.f32.tf32.tf32.f32 "
        "{%0,%1,%2,%3}, {%4,%5,%6,%7}, {%8,%9}, {%0,%1,%2,%3};"
        : "+f"(c[0]), "+f"(c[1]), "+f"(c[2]), "+f"(c[3])
        : "r"(a[0]), "r"(a[1]), "r"(a[2]), "r"(a[3]), "r"(b[0]), "r"(b[1]));
}

// ---------------- TF32 tensor-core GEMM --------------------------------------
// C[M,N] = A[M,K] @ W[N,K]^T + bias (opt. gelu).  fp32 in/out, tf32 mma.
// Block tile 128(M) x 64(N), K chunk 32, 256 threads = 8 warps (4x2),
// warp tile 32x32 = 2 m16 x 4 n8 fragments.
template<int KDIM, bool DOGELU>
__global__ __launch_bounds__(256, 2) void gemm_tf32(
    const float* __restrict__ A, const float* __restrict__ W,
    const float* __restrict__ bias, float* __restrict__ C, int N) {
    __shared__ uint32_t As[128][36];   // [m][k], +4 pad: frag loads conflict-free
    __shared__ uint32_t Ws[64][36];    // [n][k]

    const int tid  = threadIdx.x;
    const int warp = tid >> 5, lane = tid & 31;
    const int wm = warp & 3, wn = warp >> 2;     // 4 warps on M, 2 on N
    const int g  = lane >> 2, tg = lane & 3;     // groupID, thread-in-group
    const int m0 = blockIdx.y << 7;
    const int n0 = blockIdx.x << 6;

    float acc[2][4][4];
#pragma unroll
    for (int i = 0; i < 2; i++)
#pragma unroll
        for (int j = 0; j < 4; j++)
#pragma unroll
            for (int r = 0; r < 4; r++) acc[i][j][r] = 0.f;

    for (int k0 = 0; k0 < KDIM; k0 += 32) {
#pragma unroll
        for (int j = 0; j < 4; j++) {
            int s = tid + (j << 8);
            int r = s >> 3, c4 = s & 7;
            float4 v = *(const float4*)&A[(size_t)(m0 + r) * KDIM + k0 + (c4 << 2)];
            uint4 u = make_uint4(f2tf32(v.x), f2tf32(v.y), f2tf32(v.z), f2tf32(v.w));
            *(uint4*)&As[r][c4 << 2] = u;
        }
#pragma unroll
        for (int j = 0; j < 2; j++) {
            int s = tid + (j << 8);
            int r = s >> 3, c4 = s & 7;
            float4 v = *(const float4*)&W[(size_t)(n0 + r) * KDIM + k0 + (c4 << 2)];
            uint4 u = make_uint4(f2tf32(v.x), f2tf32(v.y), f2tf32(v.z), f2tf32(v.w));
            *(uint4*)&Ws[r][c4 << 2] = u;
        }
        __syncthreads();

#pragma unroll
        for (int ks = 0; ks < 4; ks++) {
            const int kb = ks << 3;
            uint32_t a[2][4], b[4][2];
#pragma unroll
            for (int mt = 0; mt < 2; mt++) {
                int row = (wm << 5) + (mt << 4);
                a[mt][0] = As[row + g    ][kb + tg];
                a[mt][1] = As[row + g + 8][kb + tg];
                a[mt][2] = As[row + g    ][kb + tg + 4];
                a[mt][3] = As[row + g + 8][kb + tg + 4];
            }
#pragma unroll
            for (int nt = 0; nt < 4; nt++) {
                int col = (wn << 5) + (nt << 3);
                b[nt][0] = Ws[col + g][kb + tg];
                b[nt][1] = Ws[col + g][kb + tg + 4];
            }
#pragma unroll
            for (int mt = 0; mt < 2; mt++)
#pragma unroll
                for (int nt = 0; nt < 4; nt++)
                    mma_tf32(acc[mt][nt], a[mt], b[nt]);
        }
        __syncthreads();
    }

#pragma unroll
    for (int mt = 0; mt < 2; mt++) {
        int row0 = m0 + (wm << 5) + (mt << 4) + g;
#pragma unroll
        for (int nt = 0; nt < 4; nt++) {
            int col = n0 + (wn << 5) + (nt << 3) + (tg << 1);
            float b0 = __ldg(&bias[col]);
            float b1 = __ldg(&bias[col + 1]);
            float v00 = acc[mt][nt][0] + b0, v01 = acc[mt][nt][1] + b1;
            float v10 = acc[mt][nt][2] + b0, v11 = acc[mt][nt][3] + b1;
            if (DOGELU) {
                v00 = gelu_tanh(v00); v01 = gelu_tanh(v01);
                v10 = gelu_tanh(v10); v11 = gelu_tanh(v11);
            }
            *(float2*)&C[(size_t)row0 * N + col]       = make_float2(v00, v01);
            *(float2*)&C[(size_t)(row0 + 8) * N + col] = make_float2(v10, v11);
        }
    }
}

// ---------------- fused residual + LayerNorm (D=128, warp per row) -----------
__global__ __launch_bounds__(256) void res_ln(
    const float* __restrict__ X, const float* __restrict__ P,
    const float* __restrict__ g, const float* __restrict__ b,
    float* __restrict__ O) {
    int row  = blockIdx.x * 8 + (threadIdx.x >> 5);
    int lane = threadIdx.x & 31;
    const float4* x4 = (const float4*)(X + (size_t)row * 128);
    const float4* p4 = (const float4*)(P + (size_t)row * 128);
    float4 xv = x4[lane];
    float4 pv = p4[lane];
    float v[4] = {xv.x + pv.x, xv.y + pv.y, xv.z + pv.z, xv.w + pv.w};
    float s  = v[0] + v[1] + v[2] + v[3];
    float ss = v[0]*v[0] + v[1]*v[1] + v[2]*v[2] + v[3]*v[3];
#pragma unroll
    for (int o = 16; o > 0; o >>= 1) {
        s  += __shfl_xor_sync(0xffffffffu, s,  o);
        ss += __shfl_xor_sync(0xffffffffu, ss, o);
    }
    float mean = s * (1.0f / 128.0f);
    float var  = ss * (1.0f / 128.0f) - mean * mean;
    float rstd = rsqrtf(var + 1e-5f);
    float4 g4 = ((const float4*)g)[lane];
    float4 b4 = ((const float4*)b)[lane];
    float4 o4;
    o4.x = (v[0] - mean) * rstd * g4.x + b4.x;
    o4.y = (v[1] - mean) * rstd * g4.y + b4.y;
    o4.z = (v[2] - mean) * rstd * g4.z + b4.z;
    o4.w = (v[3] - mean) * rstd * g4.w + b4.w;
    ((float4*)(O + (size_t)row * 128))[lane] = o4;
}

// ---------------- bias transpose ---------------------------------------------
__global__ void transpose_bias(const float* __restrict__ in, float* __restrict__ out) {
    __shared__ float tile[32][33];
    int bx = blockIdx.x << 5, by = blockIdx.y << 5;
    int x = bx + threadIdx.x;
#pragma unroll
    for (int j = 0; j < 32; j += 8) {
        int y = by + threadIdx.y + j;
        if (x < NS && y < NS) tile[threadIdx.y + j][threadIdx.x] = in[(size_t)y * NS + x];
    }
    __syncthreads();
    x = by + threadIdx.x;
#pragma unroll
    for (int j = 0; j < 32; j += 8) {
        int y = bx + threadIdx.y + j;
        if (x < NS && y < NS) out[(size_t)y * NS + x] = tile[threadIdx.x][threadIdx.y + j];
    }
}

// ---------------- temporal attention (seqlen T=12) ---------------------------
__global__ __launch_bounds__(96) void temporal_attn(
    const float* __restrict__ QKV, float* __restrict__ Out) {
    __shared__ float s[TT * 384];
    int n = blockIdx.x;
    int b = blockIdx.y;
    for (int idx = threadIdx.x; idx < TT * 384; idx += 96) {
        int t = idx / 384, c = idx % 384;
        s[idx] = QKV[((size_t)(b * TT + t) * NS + n) * 384 + c];
    }
    __syncthreads();

    int h = threadIdx.x / TT;
    int q = threadIdx.x % TT;

    float qr[16];
#pragma unroll
    for (int d = 0; d < 16; d++) qr[d] = s[q * 384 + h * 16 + d];

    float sc[TT];
    float mx = -1e30f;
#pragma unroll
    for (int t2 = 0; t2 < TT; t2++) {
        const float* kr = &s[t2 * 384 + 128 + h * 16];
        float dot = 0.f;
#pragma unroll
        for (int d = 0; d < 16; d++) dot += qr[d] * kr[d];
        sc[t2] = dot * 0.25f;
        mx = fmaxf(mx, sc[t2]);
    }
    float l = 0.f;
#pragma unroll
    for (int t2 = 0; t2 < TT; t2++) {
        sc[t2] = __expf(sc[t2] - mx);
        l += sc[t2];
    }
    float acc[16] = {};
#pragma unroll
    for (int t2 = 0; t2 < TT; t2++) {
        float p = sc[t2];
        const float* vr = &s[t2 * 384 + 256 + h * 16];
#pragma unroll
        for (int d = 0; d < 16; d++) acc[d] += p * vr[d];
    }
    float inv = 1.f / l;
    float* op = &Out[((size_t)(b * TT + q) * NS + n) * 128 + h * 16];
#pragma unroll
    for (int d = 0; d < 16; d++) op[d] = acc[d] * inv;
}

// ---------------- spatial attention (seqlen N=325, +graph bias) --------------
__global__ __launch_bounds__(128) void spatial_attn(
    const float* __restrict__ QKV, const float* __restrict__ BiasT,
    float* __restrict__ Out) {
    __shared__ float Ks[NS * 16];
    __shared__ float Vs[NS * 16];
    int h  = blockIdx.y;
    int bt = blockIdx.z;
    size_t base = (size_t)bt * NS;
    for (int idx = threadIdx.x; idx < NS * 16; idx += 128) {
        int nn = idx >> 4, d = idx & 15;
        Ks[idx] = QKV[(base + nn) * 384 + 128 + h * 16 + d];
        Vs[idx] = QKV[(base + nn) * 384 + 256 + h * 16 + d];
    }
    __syncthreads();

    int q = blockIdx.x * 128 + threadIdx.x;
    if (q >= NS) return;

    float qr[16];
    const float* qp = &QKV[(base + q) * 384 + h * 16];
#pragma unroll
    for (int d = 0; d < 16; d++) qr[d] = qp[d];

    float l = 0.f;
    float acc[16] = {};
    for (int nn = 0; nn < NS; nn++) {
        const float4* kr = (const float4*)&Ks[nn * 16];
        float dot = 0.f;
#pragma unroll
        for (int c = 0; c < 4; c++) {
            float4 k4 = kr[c];
            dot += qr[c*4+0]*k4.x + qr[c*4+1]*k4.y + qr[c*4+2]*k4.z + qr[c*4+3]*k4.w;
        }
        float p = __expf(dot * 0.25f + BiasT[(size_t)nn * NS + q]);
        l += p;
        const float4* vr = (const float4*)&Vs[nn * 16];
#pragma unroll
        for (int c = 0; c < 4; c++) {
            float4 v4 = vr[c];
            acc[c*4+0] += p * v4.x; acc[c*4+1] += p * v4.y;
            acc[c*4+2] += p * v4.z; acc[c*4+3] += p * v4.w;
        }
    }
    float inv = 1.f / l;
    float* op = &Out[(base + q) * 128 + h * 16];
#pragma unroll
    for (int d = 0; d < 16; d++) op[d] = acc[d] * inv;
}

// ---------------- driver ------------------------------------------------------
extern "C" void kernel_launch(void* const* d_in, const int* in_sizes, int n_in,
                              void* d_out, int out_size) {
    const float* x        = (const float*)d_in[0];
    const float* t_w_in   = (const float*)d_in[1];
    const float* t_b_in   = (const float*)d_in[2];
    const float* t_w_out  = (const float*)d_in[3];
    const float* t_b_out  = (const float*)d_in[4];
    const float* s_w_in   = (const float*)d_in[5];
    const float* s_b_in   = (const float*)d_in[6];
    const float* s_w_out  = (const float*)d_in[7];
    const float* s_b_out  = (const float*)d_in[8];
    const float* g_bias   = (const float*)d_in[9];
    const float* norm_t_g = (const float*)d_in[10];
    const float* norm_t_b = (const float*)d_in[11];
    const float* norm_s_g = (const float*)d_in[12];
    const float* norm_s_b = (const float*)d_in[13];
    const float* ff_w1    = (const float*)d_in[14];
    const float* ff_b1    = (const float*)d_in[15];
    const float* ff_w2    = (const float*)d_in[16];
    const float* ff_b2    = (const float*)d_in[17];
    const float* norm_f_g = (const float*)d_in[18];
    const float* norm_f_b = (const float*)d_in[19];
    float* out = (float*)d_out;

    float *buf, *attn, *x1, *x2, *proj, *biasT;
    cudaGetSymbolAddress((void**)&buf,   g_buf);
    cudaGetSymbolAddress((void**)&attn,  g_attn);
    cudaGetSymbolAddress((void**)&x1,    g_x1);
    cudaGetSymbolAddress((void**)&x2,    g_x2);
    cudaGetSymbolAddress((void**)&proj,  g_proj);
    cudaGetSymbolAddress((void**)&biasT, g_biasT);

    const int MB = MTOK / 128;   // 975

    transpose_bias<<<dim3(11, 11), dim3(32, 8)>>>(g_bias, biasT);

    // --- temporal block ---
    gemm_tf32<128, false><<<dim3(6, MB), 256>>>(x, t_w_in, t_b_in, buf, 384);
    temporal_attn<<<dim3(NS, BB), 96>>>(buf, attn);
    gemm_tf32<128, false><<<dim3(2, MB), 256>>>(attn, t_w_out, t_b_out, proj, 128);
    res_ln<<<MTOK / 8, 256>>>(x, proj, norm_t_g, norm_t_b, x1);

    // --- spatial block ---
    gemm_tf32<128, false><<<dim3(6, MB), 256>>>(x1, s_w_in, s_b_in, buf, 384);
    spatial_attn<<<dim3(3, 8, BB * TT), 128>>>(buf, biasT, attn);
    gemm_tf32<128, false><<<dim3(2, MB), 256>>>(attn, s_w_out, s_b_out, proj, 128);
    res_ln<<<MTOK / 8, 256>>>(x1, proj, norm_s_g, norm_s_b, x2);

    // --- FFN ---
    gemm_tf32<128, true ><<<dim3(8, MB), 256>>>(x2, ff_w1, ff_b1, buf, 512);
    gemm_tf32<512, false><<<dim3(2, MB), 256>>>(buf, ff_w2, ff_b2, proj, 128);
    res_ln<<<MTOK / 8, 256>>>(x2, proj, norm_f_g, norm_f_b, out);
}

// round 5
// speedup vs baseline: 3.2270x; 1.2937x over previous
#include <cuda_runtime.h>
#include <math.h>
#include <stdint.h>

// Problem constants
#define BB 32
#define TT 12
#define NS 325
#define DD 128
#define FF 512
#define MTOK (BB*TT*NS)   // 124800 tokens, divisible by 128

// ---------------- scratch (static device allocations; no runtime alloc) ------
__device__ float g_buf  [(size_t)MTOK * 512];
__device__ float g_attn [(size_t)MTOK * 128];
__device__ float g_x1   [(size_t)MTOK * 128];
__device__ float g_x2   [(size_t)MTOK * 128];
__device__ float g_proj [(size_t)MTOK * 128];

// ---------------- helpers ----------------------------------------------------
__device__ __forceinline__ float gelu_tanh(float x) {
    float x3 = x * x * x;
    float t  = tanhf(0.7978845608028654f * (x + 0.044715f * x3));
    return 0.5f * x * (1.0f + t);
}

__device__ __forceinline__ uint32_t f2tf32(float x) {
    uint32_t r;
    asm("cvt.rna.tf32.f32 %0, %1;" : "=r"(r) : "f"(x));
    return r;
}

__device__ __forceinline__ void mma_tf32(float c[4], const uint32_t a[4], const uint32_t b[2]) {
    asm volatile(
        "mma.sync.aligned.m16n8k8.row.col.f32.tf32.tf32.f32 "
        "{%0,%1,%2,%3}, {%4,%5,%6,%7}, {%8,%9}, {%0,%1,%2,%3};"
        : "+f"(c[0]), "+f"(c[1]), "+f"(c[2]), "+f"(c[3])
        : "r"(a[0]), "r"(a[1]), "r"(a[2]), "r"(a[3]), "r"(b[0]), "r"(b[1]));
}

// ---------------- TF32 tensor-core GEMM, software pipelined -------------------
// C[M,N] = A[M,K] @ W[N,K]^T + bias (opt. gelu).
// 128(M) x 64(N) tile, K chunk 32, 256 threads = 8 warps (4 on M x 2 on N).
// k-slot remap: mma slot tg <-> physical k = 2*tg, slot tg+4 <-> 2*tg+1, so
// each operand pair is one LDS.64. Smem rows are 32 words with 16B-block XOR
// swizzle; 2 stages = exactly 48KB static. One __syncthreads per K-chunk:
// next chunk's LDG is register-staged behind the current chunk's mma.
template<int KDIM, bool DOGELU>
__global__ __launch_bounds__(256) void gemm_tf32(
    const float* __restrict__ A, const float* __restrict__ W,
    const float* __restrict__ bias, float* __restrict__ C, int N) {
    __shared__ uint32_t sA[2][128*32];
    __shared__ uint32_t sW[2][64*32];

    const int tid  = threadIdx.x;
    const int warp = tid >> 5, lane = tid & 31;
    const int wm = warp & 3, wn = warp >> 2;
    const int g  = lane >> 2, tg = lane & 3;
    const int m0 = blockIdx.y << 7;
    const int n0 = blockIdx.x << 6;

    float4 ra[4], rw[2];

    float acc[2][4][4] = {};

    // stage chunk 0 into registers
#pragma unroll
    for (int i = 0; i < 4; i++) {
        int lin = tid + (i << 8);
        int r = lin >> 3, bk = lin & 7;
        ra[i] = *(const float4*)&A[(size_t)(m0 + r) * KDIM + (bk << 2)];
    }
#pragma unroll
    for (int i = 0; i < 2; i++) {
        int lin = tid + (i << 8);
        int r = lin >> 3, bk = lin & 7;
        rw[i] = *(const float4*)&W[(size_t)(n0 + r) * KDIM + (bk << 2)];
    }

    const int NC = KDIM / 32;
    for (int c = 0; c < NC; c++) {
        const int st = c & 1;
        // STS (with rna tf32 conversion) into stage st
#pragma unroll
        for (int i = 0; i < 4; i++) {
            int lin = tid + (i << 8);
            int r = lin >> 3, bk = lin & 7;
            uint4 u = make_uint4(f2tf32(ra[i].x), f2tf32(ra[i].y),
                                 f2tf32(ra[i].z), f2tf32(ra[i].w));
            *(uint4*)&sA[st][(r << 5) + ((bk ^ (r & 7)) << 2)] = u;
        }
#pragma unroll
        for (int i = 0; i < 2; i++) {
            int lin = tid + (i << 8);
            int r = lin >> 3, bk = lin & 7;
            uint4 u = make_uint4(f2tf32(rw[i].x), f2tf32(rw[i].y),
                                 f2tf32(rw[i].z), f2tf32(rw[i].w));
            *(uint4*)&sW[st][(r << 5) + ((bk ^ (r & 7)) << 2)] = u;
        }
        __syncthreads();

        // prefetch next chunk (overlaps with mma below)
        if (c + 1 < NC) {
            const int k0 = (c + 1) << 5;
#pragma unroll
            for (int i = 0; i < 4; i++) {
                int lin = tid + (i << 8);
                int r = lin >> 3, bk = lin & 7;
                ra[i] = *(const float4*)&A[(size_t)(m0 + r) * KDIM + k0 + (bk << 2)];
            }
#pragma unroll
            for (int i = 0; i < 2; i++) {
                int lin = tid + (i << 8);
                int r = lin >> 3, bk = lin & 7;
                rw[i] = *(const float4*)&W[(size_t)(n0 + r) * KDIM + k0 + (bk << 2)];
            }
        }

        const uint32_t* As  = sA[st];
        const uint32_t* Ws_ = sW[st];
#pragma unroll
        for (int ks = 0; ks < 4; ks++) {
            const int colw = (((2 * ks + (tg >> 1)) ^ g) << 2) + ((tg & 1) << 1);
            uint32_t afr[2][4];
#pragma unroll
            for (int mt = 0; mt < 2; mt++) {
                int r = (wm << 5) + (mt << 4) + g;
                uint2 p0 = *(const uint2*)&As[(r << 5) + colw];
                uint2 p1 = *(const uint2*)&As[((r + 8) << 5) + colw];
                afr[mt][0] = p0.x; afr[mt][1] = p1.x;
                afr[mt][2] = p0.y; afr[mt][3] = p1.y;
            }
#pragma unroll
            for (int nt = 0; nt < 4; nt++) {
                int rb = (wn << 5) + (nt << 3) + g;
                uint2 pb = *(const uint2*)&Ws_[(rb << 5) + colw];
                uint32_t bfr[2] = {pb.x, pb.y};
#pragma unroll
                for (int mt = 0; mt < 2; mt++)
                    mma_tf32(acc[mt][nt], afr[mt], bfr);
            }
        }
        // no trailing sync needed: next STS targets the other stage, and the
        // sync above guarantees all warps finished the prior use of it.
    }

#pragma unroll
    for (int mt = 0; mt < 2; mt++) {
        int row0 = m0 + (wm << 5) + (mt << 4) + g;
#pragma unroll
        for (int nt = 0; nt < 4; nt++) {
            int col = n0 + (wn << 5) + (nt << 3) + (tg << 1);
            float b0 = __ldg(&bias[col]);
            float b1 = __ldg(&bias[col + 1]);
            float v00 = acc[mt][nt][0] + b0, v01 = acc[mt][nt][1] + b1;
            float v10 = acc[mt][nt][2] + b0, v11 = acc[mt][nt][3] + b1;
            if (DOGELU) {
                v00 = gelu_tanh(v00); v01 = gelu_tanh(v01);
                v10 = gelu_tanh(v10); v11 = gelu_tanh(v11);
            }
            *(float2*)&C[(size_t)row0 * N + col]       = make_float2(v00, v01);
            *(float2*)&C[(size_t)(row0 + 8) * N + col] = make_float2(v10, v11);
        }
    }
}

// ---------------- fused residual + LayerNorm (D=128, warp per row) -----------
__global__ __launch_bounds__(256) void res_ln(
    const float* __restrict__ X, const float* __restrict__ P,
    const float* __restrict__ g, const float* __restrict__ b,
    float* __restrict__ O) {
    int row  = blockIdx.x * 8 + (threadIdx.x >> 5);
    int lane = threadIdx.x & 31;
    const float4* x4 = (const float4*)(X + (size_t)row * 128);
    const float4* p4 = (const float4*)(P + (size_t)row * 128);
    float4 xv = x4[lane];
    float4 pv = p4[lane];
    float v[4] = {xv.x + pv.x, xv.y + pv.y, xv.z + pv.z, xv.w + pv.w};
    float s  = v[0] + v[1] + v[2] + v[3];
    float ss = v[0]*v[0] + v[1]*v[1] + v[2]*v[2] + v[3]*v[3];
#pragma unroll
    for (int o = 16; o > 0; o >>= 1) {
        s  += __shfl_xor_sync(0xffffffffu, s,  o);
        ss += __shfl_xor_sync(0xffffffffu, ss, o);
    }
    float mean = s * (1.0f / 128.0f);
    float var  = ss * (1.0f / 128.0f) - mean * mean;
    float rstd = rsqrtf(var + 1e-5f);
    float4 g4 = ((const float4*)g)[lane];
    float4 b4 = ((const float4*)b)[lane];
    float4 o4;
    o4.x = (v[0] - mean) * rstd * g4.x + b4.x;
    o4.y = (v[1] - mean) * rstd * g4.y + b4.y;
    o4.z = (v[2] - mean) * rstd * g4.z + b4.z;
    o4.w = (v[3] - mean) * rstd * g4.w + b4.w;
    ((float4*)(O + (size_t)row * 128))[lane] = o4;
}

// ---------------- temporal attention (seqlen T=12) ---------------------------
__global__ __launch_bounds__(96) void temporal_attn(
    const float* __restrict__ QKV, float* __restrict__ Out) {
    __shared__ float s[TT * 384];
    int n = blockIdx.x;
    int b = blockIdx.y;
    for (int idx = threadIdx.x; idx < TT * 384; idx += 96) {
        int t = idx / 384, c = idx % 384;
        s[idx] = QKV[((size_t)(b * TT + t) * NS + n) * 384 + c];
    }
    __syncthreads();

    int h = threadIdx.x / TT;
    int q = threadIdx.x % TT;

    float qr[16];
#pragma unroll
    for (int d = 0; d < 16; d++) qr[d] = s[q * 384 + h * 16 + d];

    float sc[TT];
    float mx = -1e30f;
#pragma unroll
    for (int t2 = 0; t2 < TT; t2++) {
        const float* kr = &s[t2 * 384 + 128 + h * 16];
        float dot = 0.f;
#pragma unroll
        for (int d = 0; d < 16; d++) dot += qr[d] * kr[d];
        sc[t2] = dot * 0.25f;
        mx = fmaxf(mx, sc[t2]);
    }
    float l = 0.f;
#pragma unroll
    for (int t2 = 0; t2 < TT; t2++) {
        sc[t2] = __expf(sc[t2] - mx);
        l += sc[t2];
    }
    float acc[16] = {};
#pragma unroll
    for (int t2 = 0; t2 < TT; t2++) {
        float p = sc[t2];
        const float* vr = &s[t2 * 384 + 256 + h * 16];
#pragma unroll
        for (int d = 0; d < 16; d++) acc[d] += p * vr[d];
    }
    float inv = 1.f / l;
    float* op = &Out[((size_t)(b * TT + q) * NS + n) * 128 + h * 16];
#pragma unroll
    for (int d = 0; d < 16; d++) op[d] = acc[d] * inv;
}

// ---------------- spatial attention via tensor cores -------------------------
// Block = (h, bt), 128 threads = 4 warps. K[328x16] (stride 20) and V^T[16x332]
// staged in smem as tf32. Per 64-row q-tile (warp owns m16): loop 8-key tiles:
// S = Q@K^T (2 mma), bias + exp in fp32, O += P@V (2 mma). The k-slot remap
// (slot tg <-> phys 2tg) makes the S accumulator fragment directly usable as
// the A fragment of the PV mma: a = {c0, c2, c1, c3}. Row sums reduced over
// the tg quad by shfl; pad keys (325..327) masked; pad q rows never stored.
__global__ __launch_bounds__(128) void spatial_attn_mma(
    const float* __restrict__ QKV, const float* __restrict__ Bias,
    float* __restrict__ Out) {
    __shared__ uint32_t Ks [328 * 20];
    __shared__ uint32_t Vst[16 * 332];
    const int h  = blockIdx.x;
    const int bt = blockIdx.y;
    const size_t base = (size_t)bt * NS;
    const int tid = threadIdx.x;

    for (int idx = tid; idx < 328 * 16; idx += 128) {
        int key = idx >> 4, d = idx & 15;
        float kv = 0.f, vv = 0.f;
        if (key < NS) {
            const float* p = QKV + (base + key) * 384 + h * 16 + d;
            kv = p[128];
            vv = p[256];
        }
        Ks [key * 20 + d]   = f2tf32(kv);
        Vst[d * 332 + key]  = f2tf32(vv);
    }
    __syncthreads();

    const int warp = tid >> 5, lane = tid & 31;
    const int g = lane >> 2, tg = lane & 3;

    for (int qt = 0; qt < 6; qt++) {
        const int q0 = qt * 64 + warp * 16;
        if (q0 >= NS) break;   // whole warp out of range; no syncs below

        // Q fragments (converted once, reused over all key tiles)
        const float* Qp0 = QKV + (base + q0 + g) * 384 + h * 16;
        const float* Qp1 = Qp0 + 8 * 384;
        float2 q00 = *(const float2*)(Qp0 + 2 * tg);       // dims 2tg,2tg+1
        float2 q01 = *(const float2*)(Qp0 + 8 + 2 * tg);   // dims 8+2tg,...
        float2 q10 = *(const float2*)(Qp1 + 2 * tg);
        float2 q11 = *(const float2*)(Qp1 + 8 + 2 * tg);
        uint32_t qa0[4] = {f2tf32(q00.x), f2tf32(q10.x), f2tf32(q00.y), f2tf32(q10.y)};
        uint32_t qa1[4] = {f2tf32(q01.x), f2tf32(q11.x), f2tf32(q01.y), f2tf32(q11.y)};

        const int qr0 = min(q0 + g, NS - 1);
        const int qr1 = min(q0 + g + 8, NS - 1);
        const float* brow0 = Bias + (size_t)qr0 * NS;
        const float* brow1 = Bias + (size_t)qr1 * NS;

        float o0[4] = {0.f, 0.f, 0.f, 0.f};
        float o1[4] = {0.f, 0.f, 0.f, 0.f};
        float l0 = 0.f, l1 = 0.f;

        // main key tiles (all columns valid)
        for (int nt = 0; nt < 40; nt++) {
            const int k0 = nt * 8;
            float c[4] = {0.f, 0.f, 0.f, 0.f};
            {
                uint2 b = *(const uint2*)&Ks[(k0 + g) * 20 + 2 * tg];
                uint32_t bf[2] = {b.x, b.y};
                mma_tf32(c, qa0, bf);
            }
            {
                uint2 b = *(const uint2*)&Ks[(k0 + g) * 20 + 8 + 2 * tg];
                uint32_t bf[2] = {b.x, b.y};
                mma_tf32(c, qa1, bf);
            }
            const int col0 = k0 + 2 * tg;
            float p0 = __expf(c[0] * 0.25f + __ldg(brow0 + col0));
            float p1 = __expf(c[1] * 0.25f + __ldg(brow0 + col0 + 1));
            float p2 = __expf(c[2] * 0.25f + __ldg(brow1 + col0));
            float p3 = __expf(c[3] * 0.25f + __ldg(brow1 + col0 + 1));
            l0 += p0 + p1;
            l1 += p2 + p3;
            uint32_t pa[4] = {f2tf32(p0), f2tf32(p2), f2tf32(p1), f2tf32(p3)};
            {
                uint2 vb = *(const uint2*)&Vst[g * 332 + col0];
                uint32_t bf[2] = {vb.x, vb.y};
                mma_tf32(o0, pa, bf);
            }
            {
                uint2 vb = *(const uint2*)&Vst[(8 + g) * 332 + col0];
                uint32_t bf[2] = {vb.x, vb.y};
                mma_tf32(o1, pa, bf);
            }
        }
        // tail tile k0 = 320 (columns 320..327; valid < 325)
        {
            const int k0 = 320;
            float c[4] = {0.f, 0.f, 0.f, 0.f};
            {
                uint2 b = *(const uint2*)&Ks[(k0 + g) * 20 + 2 * tg];
                uint32_t bf[2] = {b.x, b.y};
                mma_tf32(c, qa0, bf);
            }
            {
                uint2 b = *(const uint2*)&Ks[(k0 + g) * 20 + 8 + 2 * tg];
                uint32_t bf[2] = {b.x, b.y};
                mma_tf32(c, qa1, bf);
            }
            const int col0 = k0 + 2 * tg;
            const int col1 = col0 + 1;
            float p0 = (col0 < NS) ? __expf(c[0] * 0.25f + __ldg(brow0 + col0)) : 0.f;
            float p1 = (col1 < NS) ? __expf(c[1] * 0.25f + __ldg(brow0 + col1)) : 0.f;
            float p2 = (col0 < NS) ? __expf(c[2] * 0.25f + __ldg(brow1 + col0)) : 0.f;
            float p3 = (col1 < NS) ? __expf(c[3] * 0.25f + __ldg(brow1 + col1)) : 0.f;
            l0 += p0 + p1;
            l1 += p2 + p3;
            uint32_t pa[4] = {f2tf32(p0), f2tf32(p2), f2tf32(p1), f2tf32(p3)};
            {
                uint2 vb = *(const uint2*)&Vst[g * 332 + col0];
                uint32_t bf[2] = {vb.x, vb.y};
                mma_tf32(o0, pa, bf);
            }
            {
                uint2 vb = *(const uint2*)&Vst[(8 + g) * 332 + col0];
                uint32_t bf[2] = {vb.x, vb.y};
                mma_tf32(o1, pa, bf);
            }
        }

        // reduce row sums over the tg quad (lanes g*4+tg, xor 1 and 2)
        l0 += __shfl_xor_sync(0xffffffffu, l0, 1);
        l0 += __shfl_xor_sync(0xffffffffu, l0, 2);
        l1 += __shfl_xor_sync(0xffffffffu, l1, 1);
        l1 += __shfl_xor_sync(0xffffffffu, l1, 2);
        float inv0 = 1.f / l0;
        float inv1 = 1.f / l1;

        if (q0 + g < NS) {
            float* op = Out + (base + q0 + g) * 128 + h * 16;
            *(float2*)(op + 2 * tg)     = make_float2(o0[0] * inv0, o0[1] * inv0);
            *(float2*)(op + 8 + 2 * tg) = make_float2(o1[0] * inv0, o1[1] * inv0);
        }
        if (q0 + g + 8 < NS) {
            float* op = Out + (base + q0 + g + 8) * 128 + h * 16;
            *(float2*)(op + 2 * tg)     = make_float2(o0[2] * inv1, o0[3] * inv1);
            *(float2*)(op + 8 + 2 * tg) = make_float2(o1[2] * inv1, o1[3] * inv1);
        }
    }
}

// ---------------- driver ------------------------------------------------------
extern "C" void kernel_launch(void* const* d_in, const int* in_sizes, int n_in,
                              void* d_out, int out_size) {
    const float* x        = (const float*)d_in[0];
    const float* t_w_in   = (const float*)d_in[1];
    const float* t_b_in   = (const float*)d_in[2];
    const float* t_w_out  = (const float*)d_in[3];
    const float* t_b_out  = (const float*)d_in[4];
    const float* s_w_in   = (const float*)d_in[5];
    const float* s_b_in   = (const float*)d_in[6];
    const float* s_w_out  = (const float*)d_in[7];
    const float* s_b_out  = (const float*)d_in[8];
    const float* g_bias   = (const float*)d_in[9];
    const float* norm_t_g = (const float*)d_in[10];
    const float* norm_t_b = (const float*)d_in[11];
    const float* norm_s_g = (const float*)d_in[12];
    const float* norm_s_b = (const float*)d_in[13];
    const float* ff_w1    = (const float*)d_in[14];
    const float* ff_b1    = (const float*)d_in[15];
    const float* ff_w2    = (const float*)d_in[16];
    const float* ff_b2    = (const float*)d_in[17];
    const float* norm_f_g = (const float*)d_in[18];
    const float* norm_f_b = (const float*)d_in[19];
    float* out = (float*)d_out;

    float *buf, *attn, *x1, *x2, *proj;
    cudaGetSymbolAddress((void**)&buf,   g_buf);
    cudaGetSymbolAddress((void**)&attn,  g_attn);
    cudaGetSymbolAddress((void**)&x1,    g_x1);
    cudaGetSymbolAddress((void**)&x2,    g_x2);
    cudaGetSymbolAddress((void**)&proj,  g_proj);

    const int MB = MTOK / 128;   // 975

    // --- temporal block ---
    gemm_tf32<128, false><<<dim3(6, MB), 256>>>(x, t_w_in, t_b_in, buf, 384);
    temporal_attn<<<dim3(NS, BB), 96>>>(buf, attn);
    gemm_tf32<128, false><<<dim3(2, MB), 256>>>(attn, t_w_out, t_b_out, proj, 128);
    res_ln<<<MTOK / 8, 256>>>(x, proj, norm_t_g, norm_t_b, x1);

    // --- spatial block ---
    gemm_tf32<128, false><<<dim3(6, MB), 256>>>(x1, s_w_in, s_b_in, buf, 384);
    spatial_attn_mma<<<dim3(8, BB * TT), 128>>>(buf, g_bias, attn);
    gemm_tf32<128, false><<<dim3(2, MB), 256>>>(attn, s_w_out, s_b_out, proj, 128);
    res_ln<<<MTOK / 8, 256>>>(x1, proj, norm_s_g, norm_s_b, x2);

    // --- FFN ---
    gemm_tf32<128, true ><<<dim3(8, MB), 256>>>(x2, ff_w1, ff_b1, buf, 512);
    gemm_tf32<512, false><<<dim3(2, MB), 256>>>(buf, ff_w2, ff_b2, proj, 128);
    res_ln<<<MTOK / 8, 256>>>(x2, proj, norm_f_g, norm_f_b, out);
}

// round 6
// speedup vs baseline: 3.7030x; 1.1475x over previous
#include <cuda_runtime.h>
#include <math.h>
#include <stdint.h>

// Problem constants
#define BB 32
#define TT 12
#define NS 325
#define DD 128
#define FF 512
#define MTOK (BB*TT*NS)   // 124800 tokens, divisible by 128

// ---------------- scratch (static device allocations; no runtime alloc) ------
__device__ float g_buf  [(size_t)MTOK * 512];
__device__ float g_attn [(size_t)MTOK * 128];
__device__ float g_x1   [(size_t)MTOK * 128];
__device__ float g_x2   [(size_t)MTOK * 128];
__device__ float g_proj [(size_t)MTOK * 128];

// ---------------- helpers ----------------------------------------------------
__device__ __forceinline__ float gelu_tanh(float x) {
    float x3 = x * x * x;
    float t  = tanhf(0.7978845608028654f * (x + 0.044715f * x3));
    return 0.5f * x * (1.0f + t);
}

__device__ __forceinline__ uint32_t f2tf32(float x) {
    uint32_t r;
    asm("cvt.rna.tf32.f32 %0, %1;" : "=r"(r) : "f"(x));
    return r;
}

__device__ __forceinline__ void mma_tf32(float c[4], const uint32_t a[4], const uint32_t b[2]) {
    asm volatile(
        "mma.sync.aligned.m16n8k8.row.col.f32.tf32.tf32.f32 "
        "{%0,%1,%2,%3}, {%4,%5,%6,%7}, {%8,%9}, {%0,%1,%2,%3};"
        : "+f"(c[0]), "+f"(c[1]), "+f"(c[2]), "+f"(c[3])
        : "r"(a[0]), "r"(a[1]), "r"(a[2]), "r"(a[3]), "r"(b[0]), "r"(b[1]));
}

__device__ __forceinline__ void cp_async16(uint32_t smem_addr, const void* gptr) {
    asm volatile("cp.async.cg.shared.global [%0], [%1], 16;\n"
                 :: "r"(smem_addr), "l"(gptr));
}
__device__ __forceinline__ void cp_commit() {
    asm volatile("cp.async.commit_group;\n" ::: "memory");
}
template<int N>
__device__ __forceinline__ void cp_wait() {
    asm volatile("cp.async.wait_group %0;\n" :: "n"(N) : "memory");
}

// ---------------- TF32 tensor-core GEMM, cp.async 3-stage pipeline ------------
// C[M,N] = A[M,K] @ W[N,K]^T + bias (opt. gelu).
// 128(M) x 64(N) tile, K chunk 32, 256 threads = 8 warps (4 on M x 2 on N).
// GMEM->SMEM via cp.async.cg (raw fp32; mma.tf32 HW-truncates mantissa).
// 3 stages in dynamic smem (72KB) keep 2 chunks in flight; one syncthreads
// per chunk. k-slot remap (mma slot tg <-> physical k=2*tg) keeps every
// fragment operand pair a single LDS.64. 16B-block XOR swizzle per row.
#define STAGE_WORDS 6144   // (128 + 64) * 32
#define GEMM_SMEM_BYTES (3 * STAGE_WORDS * 4)

template<int KDIM, bool DOGELU>
__global__ __launch_bounds__(256, 3) void gemm_tf32(
    const float* __restrict__ A, const float* __restrict__ W,
    const float* __restrict__ bias, float* __restrict__ C, int N) {
    extern __shared__ uint32_t sm[];

    const int tid  = threadIdx.x;
    const int warp = tid >> 5, lane = tid & 31;
    const int wm = warp & 3, wn = warp >> 2;
    const int g  = lane >> 2, tg = lane & 3;
    const int m0 = blockIdx.y << 7;
    const int n0 = blockIdx.x << 6;

    // per-thread copy coordinates (16B per cp.async)
    const int rA = tid >> 3;            // A: rows rA, rA+32, rA+64, rA+96
    const int rW = tid >> 3;            // W: rows rW (0..31), rW+32
    const int bk = tid & 7;             // 16B block within 32-word row

    auto issue = [&](int c) {
        const int st = c % 3;
        const int k0 = c << 5;
        uint32_t baseA = (uint32_t)__cvta_generic_to_shared(&sm[st * STAGE_WORDS]);
        uint32_t baseW = baseA + 4096 * 4;
#pragma unroll
        for (int i = 0; i < 4; i++) {
            int r = rA + (i << 5);
            cp_async16(baseA + (((r << 5) + ((bk ^ (r & 7)) << 2)) << 2),
                       &A[(size_t)(m0 + r) * KDIM + k0 + (bk << 2)]);
        }
#pragma unroll
        for (int i = 0; i < 2; i++) {
            int r = rW + (i << 5);
            cp_async16(baseW + (((r << 5) + ((bk ^ (r & 7)) << 2)) << 2),
                       &W[(size_t)(n0 + r) * KDIM + k0 + (bk << 2)]);
        }
        cp_commit();
    };

    float acc[2][4][4] = {};

    const int NC = KDIM / 32;
    issue(0);
    if (NC > 1) issue(1);

    for (int c = 0; c < NC; c++) {
        if (c == NC - 1) cp_wait<0>(); else cp_wait<1>();
        __syncthreads();
        if (c + 2 < NC) issue(c + 2);

        const uint32_t* As  = &sm[(c % 3) * STAGE_WORDS];
        const uint32_t* Ws_ = As + 4096;
#pragma unroll
        for (int ks = 0; ks < 4; ks++) {
            const int colw = (((2 * ks + (tg >> 1)) ^ g) << 2) + ((tg & 1) << 1);
            uint32_t afr[2][4];
#pragma unroll
            for (int mt = 0; mt < 2; mt++) {
                int r = (wm << 5) + (mt << 4) + g;
                uint2 p0 = *(const uint2*)&As[(r << 5) + colw];
                uint2 p1 = *(const uint2*)&As[((r + 8) << 5) + colw];
                afr[mt][0] = p0.x; afr[mt][1] = p1.x;
                afr[mt][2] = p0.y; afr[mt][3] = p1.y;
            }
#pragma unroll
            for (int nt = 0; nt < 4; nt++) {
                int rb = (wn << 5) + (nt << 3) + g;
                uint2 pb = *(const uint2*)&Ws_[(rb << 5) + colw];
                uint32_t bfr[2] = {pb.x, pb.y};
#pragma unroll
                for (int mt = 0; mt < 2; mt++)
                    mma_tf32(acc[mt][nt], afr[mt], bfr);
            }
        }
        __syncthreads();   // stage (c%3) fully consumed before issue(c+3) rewrites it
    }

#pragma unroll
    for (int mt = 0; mt < 2; mt++) {
        int row0 = m0 + (wm << 5) + (mt << 4) + g;
#pragma unroll
        for (int nt = 0; nt < 4; nt++) {
            int col = n0 + (wn << 5) + (nt << 3) + (tg << 1);
            float b0 = __ldg(&bias[col]);
            float b1 = __ldg(&bias[col + 1]);
            float v00 = acc[mt][nt][0] + b0, v01 = acc[mt][nt][1] + b1;
            float v10 = acc[mt][nt][2] + b0, v11 = acc[mt][nt][3] + b1;
            if (DOGELU) {
                v00 = gelu_tanh(v00); v01 = gelu_tanh(v01);
                v10 = gelu_tanh(v10); v11 = gelu_tanh(v11);
            }
            *(float2*)&C[(size_t)row0 * N + col]       = make_float2(v00, v01);
            *(float2*)&C[(size_t)(row0 + 8) * N + col] = make_float2(v10, v11);
        }
    }
}

// ---------------- fused residual + LayerNorm (D=128, warp per row) -----------
__global__ __launch_bounds__(256) void res_ln(
    const float* __restrict__ X, const float* __restrict__ P,
    const float* __restrict__ g, const float* __restrict__ b,
    float* __restrict__ O) {
    int row  = blockIdx.x * 8 + (threadIdx.x >> 5);
    int lane = threadIdx.x & 31;
    const float4* x4 = (const float4*)(X + (size_t)row * 128);
    const float4* p4 = (const float4*)(P + (size_t)row * 128);
    float4 xv = x4[lane];
    float4 pv = p4[lane];
    float v[4] = {xv.x + pv.x, xv.y + pv.y, xv.z + pv.z, xv.w + pv.w};
    float s  = v[0] + v[1] + v[2] + v[3];
    float ss = v[0]*v[0] + v[1]*v[1] + v[2]*v[2] + v[3]*v[3];
#pragma unroll
    for (int o = 16; o > 0; o >>= 1) {
        s  += __shfl_xor_sync(0xffffffffu, s,  o);
        ss += __shfl_xor_sync(0xffffffffu, ss, o);
    }
    float mean = s * (1.0f / 128.0f);
    float var  = ss * (1.0f / 128.0f) - mean * mean;
    float rstd = rsqrtf(var + 1e-5f);
    float4 g4 = ((const float4*)g)[lane];
    float4 b4 = ((const float4*)b)[lane];
    float4 o4;
    o4.x = (v[0] - mean) * rstd * g4.x + b4.x;
    o4.y = (v[1] - mean) * rstd * g4.y + b4.y;
    o4.z = (v[2] - mean) * rstd * g4.z + b4.z;
    o4.w = (v[3] - mean) * rstd * g4.w + b4.w;
    ((float4*)(O + (size_t)row * 128))[lane] = o4;
}

// ---------------- temporal attention (seqlen T=12) ---------------------------
__global__ __launch_bounds__(96) void temporal_attn(
    const float* __restrict__ QKV, float* __restrict__ Out) {
    __shared__ float s[TT * 384];
    int n = blockIdx.x;
    int b = blockIdx.y;
    for (int idx = threadIdx.x; idx < TT * 384; idx += 96) {
        int t = idx / 384, c = idx % 384;
        s[idx] = QKV[((size_t)(b * TT + t) * NS + n) * 384 + c];
    }
    __syncthreads();

    int h = threadIdx.x / TT;
    int q = threadIdx.x % TT;

    float qr[16];
#pragma unroll
    for (int d = 0; d < 16; d++) qr[d] = s[q * 384 + h * 16 + d];

    float sc[TT];
    float mx = -1e30f;
#pragma unroll
    for (int t2 = 0; t2 < TT; t2++) {
        const float* kr = &s[t2 * 384 + 128 + h * 16];
        float dot = 0.f;
#pragma unroll
        for (int d = 0; d < 16; d++) dot += qr[d] * kr[d];
        sc[t2] = dot * 0.25f;
        mx = fmaxf(mx, sc[t2]);
    }
    float l = 0.f;
#pragma unroll
    for (int t2 = 0; t2 < TT; t2++) {
        sc[t2] = __expf(sc[t2] - mx);
        l += sc[t2];
    }
    float acc[16] = {};
#pragma unroll
    for (int t2 = 0; t2 < TT; t2++) {
        float p = sc[t2];
        const float* vr = &s[t2 * 384 + 256 + h * 16];
#pragma unroll
        for (int d = 0; d < 16; d++) acc[d] += p * vr[d];
    }
    float inv = 1.f / l;
    float* op = &Out[((size_t)(b * TT + q) * NS + n) * 128 + h * 16];
#pragma unroll
    for (int d = 0; d < 16; d++) op[d] = acc[d] * inv;
}

// ---------------- spatial attention via tensor cores -------------------------
__global__ __launch_bounds__(128) void spatial_attn_mma(
    const float* __restrict__ QKV, const float* __restrict__ Bias,
    float* __restrict__ Out) {
    __shared__ uint32_t Ks [328 * 20];
    __shared__ uint32_t Vst[16 * 332];
    const int h  = blockIdx.x;
    const int bt = blockIdx.y;
    const size_t base = (size_t)bt * NS;
    const int tid = threadIdx.x;

    for (int idx = tid; idx < 328 * 16; idx += 128) {
        int key = idx >> 4, d = idx & 15;
        float kv = 0.f, vv = 0.f;
        if (key < NS) {
            const float* p = QKV + (base + key) * 384 + h * 16 + d;
            kv = p[128];
            vv = p[256];
        }
        Ks [key * 20 + d]   = f2tf32(kv);
        Vst[d * 332 + key]  = f2tf32(vv);
    }
    __syncthreads();

    const int warp = tid >> 5, lane = tid & 31;
    const int g = lane >> 2, tg = lane & 3;

    for (int qt = 0; qt < 6; qt++) {
        const int q0 = qt * 64 + warp * 16;
        if (q0 >= NS) break;

        const float* Qp0 = QKV + (base + q0 + g) * 384 + h * 16;
        const float* Qp1 = Qp0 + 8 * 384;
        float2 q00 = *(const float2*)(Qp0 + 2 * tg);
        float2 q01 = *(const float2*)(Qp0 + 8 + 2 * tg);
        float2 q10 = *(const float2*)(Qp1 + 2 * tg);
        float2 q11 = *(const float2*)(Qp1 + 8 + 2 * tg);
        uint32_t qa0[4] = {f2tf32(q00.x), f2tf32(q10.x), f2tf32(q00.y), f2tf32(q10.y)};
        uint32_t qa1[4] = {f2tf32(q01.x), f2tf32(q11.x), f2tf32(q01.y), f2tf32(q11.y)};

        const int qr0 = min(q0 + g, NS - 1);
        const int qr1 = min(q0 + g + 8, NS - 1);
        const float* brow0 = Bias + (size_t)qr0 * NS;
        const float* brow1 = Bias + (size_t)qr1 * NS;

        float o0[4] = {0.f, 0.f, 0.f, 0.f};
        float o1[4] = {0.f, 0.f, 0.f, 0.f};
        float l0 = 0.f, l1 = 0.f;

        for (int nt = 0; nt < 40; nt++) {
            const int k0 = nt * 8;
            float c[4] = {0.f, 0.f, 0.f, 0.f};
            {
                uint2 b = *(const uint2*)&Ks[(k0 + g) * 20 + 2 * tg];
                uint32_t bf[2] = {b.x, b.y};
                mma_tf32(c, qa0, bf);
            }
            {
                uint2 b = *(const uint2*)&Ks[(k0 + g) * 20 + 8 + 2 * tg];
                uint32_t bf[2] = {b.x, b.y};
                mma_tf32(c, qa1, bf);
            }
            const int col0 = k0 + 2 * tg;
            float p0 = __expf(c[0] * 0.25f + __ldg(brow0 + col0));
            float p1 = __expf(c[1] * 0.25f + __ldg(brow0 + col0 + 1));
            float p2 = __expf(c[2] * 0.25f + __ldg(brow1 + col0));
            float p3 = __expf(c[3] * 0.25f + __ldg(brow1 + col0 + 1));
            l0 += p0 + p1;
            l1 += p2 + p3;
            uint32_t pa[4] = {f2tf32(p0), f2tf32(p2), f2tf32(p1), f2tf32(p3)};
            {
                uint2 vb = *(const uint2*)&Vst[g * 332 + col0];
                uint32_t bf[2] = {vb.x, vb.y};
                mma_tf32(o0, pa, bf);
            }
            {
                uint2 vb = *(const uint2*)&Vst[(8 + g) * 332 + col0];
                uint32_t bf[2] = {vb.x, vb.y};
                mma_tf32(o1, pa, bf);
            }
        }
        {
            const int k0 = 320;
            float c[4] = {0.f, 0.f, 0.f, 0.f};
            {
                uint2 b = *(const uint2*)&Ks[(k0 + g) * 20 + 2 * tg];
                uint32_t bf[2] = {b.x, b.y};
                mma_tf32(c, qa0, bf);
            }
            {
                uint2 b = *(const uint2*)&Ks[(k0 + g) * 20 + 8 + 2 * tg];
                uint32_t bf[2] = {b.x, b.y};
                mma_tf32(c, qa1, bf);
            }
            const int col0 = k0 + 2 * tg;
            const int col1 = col0 + 1;
            float p0 = (col0 < NS) ? __expf(c[0] * 0.25f + __ldg(brow0 + col0)) : 0.f;
            float p1 = (col1 < NS) ? __expf(c[1] * 0.25f + __ldg(brow0 + col1)) : 0.f;
            float p2 = (col0 < NS) ? __expf(c[2] * 0.25f + __ldg(brow1 + col0)) : 0.f;
            float p3 = (col1 < NS) ? __expf(c[3] * 0.25f + __ldg(brow1 + col1)) : 0.f;
            l0 += p0 + p1;
            l1 += p2 + p3;
            uint32_t pa[4] = {f2tf32(p0), f2tf32(p2), f2tf32(p1), f2tf32(p3)};
            {
                uint2 vb = *(const uint2*)&Vst[g * 332 + col0];
                uint32_t bf[2] = {vb.x, vb.y};
                mma_tf32(o0, pa, bf);
            }
            {
                uint2 vb = *(const uint2*)&Vst[(8 + g) * 332 + col0];
                uint32_t bf[2] = {vb.x, vb.y};
                mma_tf32(o1, pa, bf);
            }
        }

        l0 += __shfl_xor_sync(0xffffffffu, l0, 1);
        l0 += __shfl_xor_sync(0xffffffffu, l0, 2);
        l1 += __shfl_xor_sync(0xffffffffu, l1, 1);
        l1 += __shfl_xor_sync(0xffffffffu, l1, 2);
        float inv0 = 1.f / l0;
        float inv1 = 1.f / l1;

        if (q0 + g < NS) {
            float* op = Out + (base + q0 + g) * 128 + h * 16;
            *(float2*)(op + 2 * tg)     = make_float2(o0[0] * inv0, o0[1] * inv0);
            *(float2*)(op + 8 + 2 * tg) = make_float2(o1[0] * inv0, o1[1] * inv0);
        }
        if (q0 + g + 8 < NS) {
            float* op = Out + (base + q0 + g + 8) * 128 + h * 16;
            *(float2*)(op + 2 * tg)     = make_float2(o0[2] * inv1, o0[3] * inv1);
            *(float2*)(op + 8 + 2 * tg) = make_float2(o1[2] * inv1, o1[3] * inv1);
        }
    }
}

// ---------------- driver ------------------------------------------------------
extern "C" void kernel_launch(void* const* d_in, const int* in_sizes, int n_in,
                              void* d_out, int out_size) {
    const float* x        = (const float*)d_in[0];
    const float* t_w_in   = (const float*)d_in[1];
    const float* t_b_in   = (const float*)d_in[2];
    const float* t_w_out  = (const float*)d_in[3];
    const float* t_b_out  = (const float*)d_in[4];
    const float* s_w_in   = (const float*)d_in[5];
    const float* s_b_in   = (const float*)d_in[6];
    const float* s_w_out  = (const float*)d_in[7];
    const float* s_b_out  = (const float*)d_in[8];
    const float* g_bias   = (const float*)d_in[9];
    const float* norm_t_g = (const float*)d_in[10];
    const float* norm_t_b = (const float*)d_in[11];
    const float* norm_s_g = (const float*)d_in[12];
    const float* norm_s_b = (const float*)d_in[13];
    const float* ff_w1    = (const float*)d_in[14];
    const float* ff_b1    = (const float*)d_in[15];
    const float* ff_w2    = (const float*)d_in[16];
    const float* ff_b2    = (const float*)d_in[17];
    const float* norm_f_g = (const float*)d_in[18];
    const float* norm_f_b = (const float*)d_in[19];
    float* out = (float*)d_out;

    float *buf, *attn, *x1, *x2, *proj;
    cudaGetSymbolAddress((void**)&buf,   g_buf);
    cudaGetSymbolAddress((void**)&attn,  g_attn);
    cudaGetSymbolAddress((void**)&x1,    g_x1);
    cudaGetSymbolAddress((void**)&x2,    g_x2);
    cudaGetSymbolAddress((void**)&proj,  g_proj);

    cudaFuncSetAttribute(gemm_tf32<128, false>,
                         cudaFuncAttributeMaxDynamicSharedMemorySize, GEMM_SMEM_BYTES);
    cudaFuncSetAttribute(gemm_tf32<128, true>,
                         cudaFuncAttributeMaxDynamicSharedMemorySize, GEMM_SMEM_BYTES);
    cudaFuncSetAttribute(gemm_tf32<512, false>,
                         cudaFuncAttributeMaxDynamicSharedMemorySize, GEMM_SMEM_BYTES);

    const int MB = MTOK / 128;   // 975

    // --- temporal block ---
    gemm_tf32<128, false><<<dim3(6, MB), 256, GEMM_SMEM_BYTES>>>(x, t_w_in, t_b_in, buf, 384);
    temporal_attn<<<dim3(NS, BB), 96>>>(buf, attn);
    gemm_tf32<128, false><<<dim3(2, MB), 256, GEMM_SMEM_BYTES>>>(attn, t_w_out, t_b_out, proj, 128);
    res_ln<<<MTOK / 8, 256>>>(x, proj, norm_t_g, norm_t_b, x1);

    // --- spatial block ---
    gemm_tf32<128, false><<<dim3(6, MB), 256, GEMM_SMEM_BYTES>>>(x1, s_w_in, s_b_in, buf, 384);
    spatial_attn_mma<<<dim3(8, BB * TT), 128>>>(buf, g_bias, attn);
    gemm_tf32<128, false><<<dim3(2, MB), 256, GEMM_SMEM_BYTES>>>(attn, s_w_out, s_b_out, proj, 128);
    res_ln<<<MTOK / 8, 256>>>(x1, proj, norm_s_g, norm_s_b, x2);

    // --- FFN ---
    gemm_tf32<128, true ><<<dim3(8, MB), 256, GEMM_SMEM_BYTES>>>(x2, ff_w1, ff_b1, buf, 512);
    gemm_tf32<512, false><<<dim3(2, MB), 256, GEMM_SMEM_BYTES>>>(buf, ff_w2, ff_b2, proj, 128);
    res_ln<<<MTOK / 8, 256>>>(x2, proj, norm_f_g, norm_f_b, out);
}

// round 7
// speedup vs baseline: 4.0957x; 1.1061x over previous
#include <cuda_runtime.h>
#include <math.h>
#include <stdint.h>

// Problem constants
#define BB 32
#define TT 12
#define NS 325
#define DD 128
#define FF 512
#define MTOK (BB*TT*NS)   // 124800 tokens, divisible by 128

// ---------------- scratch (static device allocations; no runtime alloc) ------
__device__ float g_buf  [(size_t)MTOK * 512];
__device__ float g_attn [(size_t)MTOK * 128];
__device__ float g_x1   [(size_t)MTOK * 128];
__device__ float g_x2   [(size_t)MTOK * 128];

// ---------------- helpers ----------------------------------------------------
__device__ __forceinline__ float gelu_tanh(float x) {
    float x3 = x * x * x;
    float t  = tanhf(0.7978845608028654f * (x + 0.044715f * x3));
    return 0.5f * x * (1.0f + t);
}

__device__ __forceinline__ uint32_t f2tf32(float x) {
    uint32_t r;
    asm("cvt.rna.tf32.f32 %0, %1;" : "=r"(r) : "f"(x));
    return r;
}

__device__ __forceinline__ void mma_tf32(float c[4], const uint32_t a[4], const uint32_t b[2]) {
    asm volatile(
        "mma.sync.aligned.m16n8k8.row.col.f32.tf32.tf32.f32 "
        "{%0,%1,%2,%3}, {%4,%5,%6,%7}, {%8,%9}, {%0,%1,%2,%3};"
        : "+f"(c[0]), "+f"(c[1]), "+f"(c[2]), "+f"(c[3])
        : "r"(a[0]), "r"(a[1]), "r"(a[2]), "r"(a[3]), "r"(b[0]), "r"(b[1]));
}

__device__ __forceinline__ void cp_async16(uint32_t smem_addr, const void* gptr) {
    asm volatile("cp.async.cg.shared.global [%0], [%1], 16;\n"
                 :: "r"(smem_addr), "l"(gptr));
}
__device__ __forceinline__ void cp_commit() {
    asm volatile("cp.async.commit_group;\n" ::: "memory");
}
template<int N>
__device__ __forceinline__ void cp_wait() {
    asm volatile("cp.async.wait_group %0;\n" :: "n"(N) : "memory");
}

// ---------------- TF32 tensor-core GEMM, cp.async 3-stage pipeline ------------
// C[M,N] = A[M,K] @ W[N,K]^T + bias, then optionally gelu (FFN1) or fused
// residual+LayerNorm (out-proj / FFN2, requires the N-tile to cover all 128
// output columns: grid.x == 1, N == 128).
// 128(M) x 128(N) tile, K chunk 32, 256 threads = 8 warps (4 on M x 2 on N),
// warp tile 32x64: mt in {0,1} (m16), nt in {0..7} (n8), acc = 64 regs.
// GMEM->SMEM via cp.async.cg (raw fp32; mma.tf32 HW-truncates mantissa).
// 3 stages x 32KB dynamic smem keep 2 chunks in flight; ONE syncthreads per
// chunk (the post-wait sync also orders stage reuse: issue(c+2) follows it,
// and any warp at iteration c+1's sync has finished iteration c's reads).
// k-slot remap (mma slot tg <-> physical k=2*tg) keeps every fragment operand
// pair a single LDS.64. 16B-block XOR swizzle per 32-word row.
#define STAGE_WORDS 8192   // (128 + 128) * 32
#define GEMM_SMEM_BYTES (3 * STAGE_WORDS * 4)

template<int KDIM, bool DOGELU, bool FUSELN>
__global__ __launch_bounds__(256, 2) void gemm_tf32(
    const float* __restrict__ A, const float* __restrict__ W,
    const float* __restrict__ bias, float* __restrict__ C, int N,
    const float* __restrict__ Xres, const float* __restrict__ gamma,
    const float* __restrict__ beta) {
    extern __shared__ uint32_t sm[];

    const int tid  = threadIdx.x;
    const int warp = tid >> 5, lane = tid & 31;
    const int wm = warp & 3, wn = warp >> 2;
    const int g  = lane >> 2, tg = lane & 3;
    const int m0 = blockIdx.y << 7;
    const int n0 = blockIdx.x << 7;

    const int rr = tid >> 3;   // copy row base (0..31)
    const int bk = tid & 7;    // 16B block within 32-word row

    auto issue = [&](int c) {
        const int st = c % 3;
        const int k0 = c << 5;
        uint32_t baseA = (uint32_t)__cvta_generic_to_shared(&sm[st * STAGE_WORDS]);
        uint32_t baseW = baseA + 4096 * 4;
#pragma unroll
        for (int i = 0; i < 4; i++) {
            int r = rr + (i << 5);
            uint32_t off = ((r << 5) + ((bk ^ (r & 7)) << 2)) << 2;
            cp_async16(baseA + off, &A[(size_t)(m0 + r) * KDIM + k0 + (bk << 2)]);
            cp_async16(baseW + off, &W[(size_t)(n0 + r) * KDIM + k0 + (bk << 2)]);
        }
        cp_commit();
    };

    float acc[2][8][4] = {};

    const int NC = KDIM / 32;
    issue(0);
    if (NC > 1) issue(1);

    for (int c = 0; c < NC; c++) {
        if (c == NC - 1) cp_wait<0>(); else cp_wait<1>();
        __syncthreads();
        if (c + 2 < NC) issue(c + 2);

        const uint32_t* As  = &sm[(c % 3) * STAGE_WORDS];
        const uint32_t* Ws_ = As + 4096;
#pragma unroll
        for (int ks = 0; ks < 4; ks++) {
            const int colw = (((2 * ks + (tg >> 1)) ^ g) << 2) + ((tg & 1) << 1);
            uint32_t afr[2][4];
#pragma unroll
            for (int mt = 0; mt < 2; mt++) {
                int r = (wm << 5) + (mt << 4) + g;
                uint2 p0 = *(const uint2*)&As[(r << 5) + colw];
                uint2 p1 = *(const uint2*)&As[((r + 8) << 5) + colw];
                afr[mt][0] = p0.x; afr[mt][1] = p1.x;
                afr[mt][2] = p0.y; afr[mt][3] = p1.y;
            }
#pragma unroll
            for (int nt = 0; nt < 8; nt++) {
                int rb = (wn << 6) + (nt << 3) + g;
                uint2 pb = *(const uint2*)&Ws_[(rb << 5) + colw];
                uint32_t bfr[2] = {pb.x, pb.y};
#pragma unroll
                for (int mt = 0; mt < 2; mt++)
                    mma_tf32(acc[mt][nt], afr[mt], bfr);
            }
        }
    }

    if (!FUSELN) {
#pragma unroll
        for (int mt = 0; mt < 2; mt++) {
            int row0 = m0 + (wm << 5) + (mt << 4) + g;
#pragma unroll
            for (int nt = 0; nt < 8; nt++) {
                int col = n0 + (wn << 6) + (nt << 3) + (tg << 1);
                float b0 = __ldg(&bias[col]);
                float b1 = __ldg(&bias[col + 1]);
                float v00 = acc[mt][nt][0] + b0, v01 = acc[mt][nt][1] + b1;
                float v10 = acc[mt][nt][2] + b0, v11 = acc[mt][nt][3] + b1;
                if (DOGELU) {
                    v00 = gelu_tanh(v00); v01 = gelu_tanh(v01);
                    v10 = gelu_tanh(v10); v11 = gelu_tanh(v11);
                }
                *(float2*)&C[(size_t)row0 * N + col]       = make_float2(v00, v01);
                *(float2*)&C[(size_t)(row0 + 8) * N + col] = make_float2(v10, v11);
            }
        }
    } else {
        // fused residual + LayerNorm over the full 128-col row (n0 == 0).
        // v = acc + bias + Xres; LN(v) * gamma + beta -> C.
        __syncthreads();                      // all warps done with smem stages
        float* red = (float*)sm;              // [128 rows][2 wn][2 {sum,ss}]

        // v values: [mt][rh][nt][2]; rows rl = wm*32+mt*16+rh*8+g
        float v[2][2][8][2];
        float psum[2][2], pss[2][2];
#pragma unroll
        for (int mt = 0; mt < 2; mt++)
#pragma unroll
            for (int rh = 0; rh < 2; rh++) {
                int row = m0 + (wm << 5) + (mt << 4) + (rh << 3) + g;
                const float* xr = Xres + (size_t)row * 128;
                float s = 0.f, ss = 0.f;
#pragma unroll
                for (int nt = 0; nt < 8; nt++) {
                    int col = (wn << 6) + (nt << 3) + (tg << 1);
                    float2 xv = *(const float2*)&xr[col];
                    float b0 = __ldg(&bias[col]);
                    float b1 = __ldg(&bias[col + 1]);
                    float v0 = acc[mt][nt][rh * 2 + 0] + b0 + xv.x;
                    float v1 = acc[mt][nt][rh * 2 + 1] + b1 + xv.y;
                    v[mt][rh][nt][0] = v0;
                    v[mt][rh][nt][1] = v1;
                    s  += v0 + v1;
                    ss += v0 * v0 + v1 * v1;
                }
                s  += __shfl_xor_sync(0xffffffffu, s, 1);
                s  += __shfl_xor_sync(0xffffffffu, s, 2);
                ss += __shfl_xor_sync(0xffffffffu, ss, 1);
                ss += __shfl_xor_sync(0xffffffffu, ss, 2);
                psum[mt][rh] = s;
                pss[mt][rh]  = ss;
            }
#pragma unroll
        for (int mt = 0; mt < 2; mt++)
#pragma unroll
            for (int rh = 0; rh < 2; rh++) {
                int rl = (wm << 5) + (mt << 4) + (rh << 3) + g;
                if (tg == 0) {
                    red[rl * 4 + wn * 2 + 0] = psum[mt][rh];
                    red[rl * 4 + wn * 2 + 1] = pss[mt][rh];
                }
            }
        __syncthreads();
#pragma unroll
        for (int mt = 0; mt < 2; mt++)
#pragma unroll
            for (int rh = 0; rh < 2; rh++) {
                int rl  = (wm << 5) + (mt << 4) + (rh << 3) + g;
                float s  = red[rl * 4 + 0] + red[rl * 4 + 2];
                float ss = red[rl * 4 + 1] + red[rl * 4 + 3];
                float mean = s * (1.0f / 128.0f);
                float var  = ss * (1.0f / 128.0f) - mean * mean;
                float rstd = rsqrtf(var + 1e-5f);
                int row = m0 + rl;
                float* op = C + (size_t)row * 128;
#pragma unroll
                for (int nt = 0; nt < 8; nt++) {
                    int col = (wn << 6) + (nt << 3) + (tg << 1);
                    float g0 = __ldg(&gamma[col]),    b0 = __ldg(&beta[col]);
                    float g1 = __ldg(&gamma[col + 1]), b1 = __ldg(&beta[col + 1]);
                    float o0 = (v[mt][rh][nt][0] - mean) * rstd * g0 + b0;
                    float o1 = (v[mt][rh][nt][1] - mean) * rstd * g1 + b1;
                    *(float2*)&op[col] = make_float2(o0, o1);
                }
            }
    }
}

// ---------------- temporal attention (seqlen T=12) ---------------------------
__global__ __launch_bounds__(96) void temporal_attn(
    const float* __restrict__ QKV, float* __restrict__ Out) {
    __shared__ float s[TT * 384];
    int n = blockIdx.x;
    int b = blockIdx.y;
    for (int idx = threadIdx.x; idx < TT * 384; idx += 96) {
        int t = idx / 384, c = idx % 384;
        s[idx] = QKV[((size_t)(b * TT + t) * NS + n) * 384 + c];
    }
    __syncthreads();

    int h = threadIdx.x / TT;
    int q = threadIdx.x % TT;

    float qr[16];
#pragma unroll
    for (int d = 0; d < 16; d++) qr[d] = s[q * 384 + h * 16 + d];

    float sc[TT];
    float mx = -1e30f;
#pragma unroll
    for (int t2 = 0; t2 < TT; t2++) {
        const float* kr = &s[t2 * 384 + 128 + h * 16];
        float dot = 0.f;
#pragma unroll
        for (int d = 0; d < 16; d++) dot += qr[d] * kr[d];
        sc[t2] = dot * 0.25f;
        mx = fmaxf(mx, sc[t2]);
    }
    float l = 0.f;
#pragma unroll
    for (int t2 = 0; t2 < TT; t2++) {
        sc[t2] = __expf(sc[t2] - mx);
        l += sc[t2];
    }
    float acc[16] = {};
#pragma unroll
    for (int t2 = 0; t2 < TT; t2++) {
        float p = sc[t2];
        const float* vr = &s[t2 * 384 + 256 + h * 16];
#pragma unroll
        for (int d = 0; d < 16; d++) acc[d] += p * vr[d];
    }
    float inv = 1.f / l;
    float* op = &Out[((size_t)(b * TT + q) * NS + n) * 128 + h * 16];
#pragma unroll
    for (int d = 0; d < 16; d++) op[d] = acc[d] * inv;
}

// ---------------- spatial attention via tensor cores -------------------------
__global__ __launch_bounds__(128) void spatial_attn_mma(
    const float* __restrict__ QKV, const float* __restrict__ Bias,
    float* __restrict__ Out) {
    __shared__ uint32_t Ks [328 * 20];
    __shared__ uint32_t Vst[16 * 332];
    const int h  = blockIdx.x;
    const int bt = blockIdx.y;
    const size_t base = (size_t)bt * NS;
    const int tid = threadIdx.x;

    for (int idx = tid; idx < 328 * 16; idx += 128) {
        int key = idx >> 4, d = idx & 15;
        float kv = 0.f, vv = 0.f;
        if (key < NS) {
            const float* p = QKV + (base + key) * 384 + h * 16 + d;
            kv = p[128];
            vv = p[256];
        }
        Ks [key * 20 + d]   = f2tf32(kv);
        Vst[d * 332 + key]  = f2tf32(vv);
    }
    __syncthreads();

    const int warp = tid >> 5, lane = tid & 31;
    const int g = lane >> 2, tg = lane & 3;

    for (int qt = 0; qt < 6; qt++) {
        const int q0 = qt * 64 + warp * 16;
        if (q0 >= NS) break;

        const float* Qp0 = QKV + (base + q0 + g) * 384 + h * 16;
        const float* Qp1 = Qp0 + 8 * 384;
        float2 q00 = *(const float2*)(Qp0 + 2 * tg);
        float2 q01 = *(const float2*)(Qp0 + 8 + 2 * tg);
        float2 q10 = *(const float2*)(Qp1 + 2 * tg);
        float2 q11 = *(const float2*)(Qp1 + 8 + 2 * tg);
        uint32_t qa0[4] = {f2tf32(q00.x), f2tf32(q10.x), f2tf32(q00.y), f2tf32(q10.y)};
        uint32_t qa1[4] = {f2tf32(q01.x), f2tf32(q11.x), f2tf32(q01.y), f2tf32(q11.y)};

        const int qr0 = min(q0 + g, NS - 1);
        const int qr1 = min(q0 + g + 8, NS - 1);
        const float* brow0 = Bias + (size_t)qr0 * NS;
        const float* brow1 = Bias + (size_t)qr1 * NS;

        float o0[4] = {0.f, 0.f, 0.f, 0.f};
        float o1[4] = {0.f, 0.f, 0.f, 0.f};
        float l0 = 0.f, l1 = 0.f;

        for (int nt = 0; nt < 40; nt++) {
            const int k0 = nt * 8;
            float c[4] = {0.f, 0.f, 0.f, 0.f};
            {
                uint2 b = *(const uint2*)&Ks[(k0 + g) * 20 + 2 * tg];
                uint32_t bf[2] = {b.x, b.y};
                mma_tf32(c, qa0, bf);
            }
            {
                uint2 b = *(const uint2*)&Ks[(k0 + g) * 20 + 8 + 2 * tg];
                uint32_t bf[2] = {b.x, b.y};
                mma_tf32(c, qa1, bf);
            }
            const int col0 = k0 + 2 * tg;
            float p0 = __expf(c[0] * 0.25f + __ldg(brow0 + col0));
            float p1 = __expf(c[1] * 0.25f + __ldg(brow0 + col0 + 1));
            float p2 = __expf(c[2] * 0.25f + __ldg(brow1 + col0));
            float p3 = __expf(c[3] * 0.25f + __ldg(brow1 + col0 + 1));
            l0 += p0 + p1;
            l1 += p2 + p3;
            uint32_t pa[4] = {f2tf32(p0), f2tf32(p2), f2tf32(p1), f2tf32(p3)};
            {
                uint2 vb = *(const uint2*)&Vst[g * 332 + col0];
                uint32_t bf[2] = {vb.x, vb.y};
                mma_tf32(o0, pa, bf);
            }
            {
                uint2 vb = *(const uint2*)&Vst[(8 + g) * 332 + col0];
                uint32_t bf[2] = {vb.x, vb.y};
                mma_tf32(o1, pa, bf);
            }
        }
        {
            const int k0 = 320;
            float c[4] = {0.f, 0.f, 0.f, 0.f};
            {
                uint2 b = *(const uint2*)&Ks[(k0 + g) * 20 + 2 * tg];
                uint32_t bf[2] = {b.x, b.y};
                mma_tf32(c, qa0, bf);
            }
            {
                uint2 b = *(const uint2*)&Ks[(k0 + g) * 20 + 8 + 2 * tg];
                uint32_t bf[2] = {b.x, b.y};
                mma_tf32(c, qa1, bf);
            }
            const int col0 = k0 + 2 * tg;
            const int col1 = col0 + 1;
            float p0 = (col0 < NS) ? __expf(c[0] * 0.25f + __ldg(brow0 + col0)) : 0.f;
            float p1 = (col1 < NS) ? __expf(c[1] * 0.25f + __ldg(brow0 + col1)) : 0.f;
            float p2 = (col0 < NS) ? __expf(c[2] * 0.25f + __ldg(brow1 + col0)) : 0.f;
            float p3 = (col1 < NS) ? __expf(c[3] * 0.25f + __ldg(brow1 + col1)) : 0.f;
            l0 += p0 + p1;
            l1 += p2 + p3;
            uint32_t pa[4] = {f2tf32(p0), f2tf32(p2), f2tf32(p1), f2tf32(p3)};
            {
                uint2 vb = *(const uint2*)&Vst[g * 332 + col0];
                uint32_t bf[2] = {vb.x, vb.y};
                mma_tf32(o0, pa, bf);
            }
            {
                uint2 vb = *(const uint2*)&Vst[(8 + g) * 332 + col0];
                uint32_t bf[2] = {vb.x, vb.y};
                mma_tf32(o1, pa, bf);
            }
        }

        l0 += __shfl_xor_sync(0xffffffffu, l0, 1);
        l0 += __shfl_xor_sync(0xffffffffu, l0, 2);
        l1 += __shfl_xor_sync(0xffffffffu, l1, 1);
        l1 += __shfl_xor_sync(0xffffffffu, l1, 2);
        float inv0 = 1.f / l0;
        float inv1 = 1.f / l1;

        if (q0 + g < NS) {
            float* op = Out + (base + q0 + g) * 128 + h * 16;
            *(float2*)(op + 2 * tg)     = make_float2(o0[0] * inv0, o0[1] * inv0);
            *(float2*)(op + 8 + 2 * tg) = make_float2(o1[0] * inv0, o1[1] * inv0);
        }
        if (q0 + g + 8 < NS) {
            float* op = Out + (base + q0 + g + 8) * 128 + h * 16;
            *(float2*)(op + 2 * tg)     = make_float2(o0[2] * inv1, o0[3] * inv1);
            *(float2*)(op + 8 + 2 * tg) = make_float2(o1[2] * inv1, o1[3] * inv1);
        }
    }
}

// ---------------- driver ------------------------------------------------------
extern "C" void kernel_launch(void* const* d_in, const int* in_sizes, int n_in,
                              void* d_out, int out_size) {
    const float* x        = (const float*)d_in[0];
    const float* t_w_in   = (const float*)d_in[1];
    const float* t_b_in   = (const float*)d_in[2];
    const float* t_w_out  = (const float*)d_in[3];
    const float* t_b_out  = (const float*)d_in[4];
    const float* s_w_in   = (const float*)d_in[5];
    const float* s_b_in   = (const float*)d_in[6];
    const float* s_w_out  = (const float*)d_in[7];
    const float* s_b_out  = (const float*)d_in[8];
    const float* g_bias   = (const float*)d_in[9];
    const float* norm_t_g = (const float*)d_in[10];
    const float* norm_t_b = (const float*)d_in[11];
    const float* norm_s_g = (const float*)d_in[12];
    const float* norm_s_b = (const float*)d_in[13];
    const float* ff_w1    = (const float*)d_in[14];
    const float* ff_b1    = (const float*)d_in[15];
    const float* ff_w2    = (const float*)d_in[16];
    const float* ff_b2    = (const float*)d_in[17];
    const float* norm_f_g = (const float*)d_in[18];
    const float* norm_f_b = (const float*)d_in[19];
    float* out = (float*)d_out;

    float *buf, *attn, *x1, *x2;
    cudaGetSymbolAddress((void**)&buf,  g_buf);
    cudaGetSymbolAddress((void**)&attn, g_attn);
    cudaGetSymbolAddress((void**)&x1,   g_x1);
    cudaGetSymbolAddress((void**)&x2,   g_x2);

    cudaFuncSetAttribute(gemm_tf32<128, false, false>,
                         cudaFuncAttributeMaxDynamicSharedMemorySize, GEMM_SMEM_BYTES);
    cudaFuncSetAttribute(gemm_tf32<128, false, true>,
                         cudaFuncAttributeMaxDynamicSharedMemorySize, GEMM_SMEM_BYTES);
    cudaFuncSetAttribute(gemm_tf32<128, true, false>,
                         cudaFuncAttributeMaxDynamicSharedMemorySize, GEMM_SMEM_BYTES);
    cudaFuncSetAttribute(gemm_tf32<512, false, true>,
                         cudaFuncAttributeMaxDynamicSharedMemorySize, GEMM_SMEM_BYTES);

    const int MB = MTOK / 128;   // 975

    // --- temporal block ---
    gemm_tf32<128, false, false><<<dim3(3, MB), 256, GEMM_SMEM_BYTES>>>(
        x, t_w_in, t_b_in, buf, 384, nullptr, nullptr, nullptr);
    temporal_attn<<<dim3(NS, BB), 96>>>(buf, attn);
    gemm_tf32<128, false, true><<<dim3(1, MB), 256, GEMM_SMEM_BYTES>>>(
        attn, t_w_out, t_b_out, x1, 128, x, norm_t_g, norm_t_b);

    // --- spatial block ---
    gemm_tf32<128, false, false><<<dim3(3, MB), 256, GEMM_SMEM_BYTES>>>(
        x1, s_w_in, s_b_in, buf, 384, nullptr, nullptr, nullptr);
    spatial_attn_mma<<<dim3(8, BB * TT), 128>>>(buf, g_bias, attn);
    gemm_tf32<128, false, true><<<dim3(1, MB), 256, GEMM_SMEM_BYTES>>>(
        attn, s_w_out, s_b_out, x2, 128, x1, norm_s_g, norm_s_b);

    // --- FFN ---
    gemm_tf32<128, true, false><<<dim3(4, MB), 256, GEMM_SMEM_BYTES>>>(
        x2, ff_w1, ff_b1, buf, 512, nullptr, nullptr, nullptr);
    gemm_tf32<512, false, true><<<dim3(1, MB), 256, GEMM_SMEM_BYTES>>>(
        buf, ff_w2, ff_b2, out, 128, x2, norm_f_g, norm_f_b);
}